// round 6
// baseline (speedup 1.0000x reference)
#include <cuda_runtime.h>
#include <cstdint>
#include <math.h>

#define CH 512
#define NG 64
#define N_SAMP 16
#define H 64
#define W 64
#define HW 4096

#define SROWS 34
#define SCOLS 68                         // 272B rows, 16B-aligned
#define CHT   (SROWS * SCOLS)            // 2312 floats
#define STILE (8 * CHT)                  // 18496 floats = 73984 B

__device__ float g_sd[N_SAMP * CH];      // style spatial mean [n,c]
__device__ float g_d[N_SAMP * 72];       // leaky(d)[n, j, ky, kx]
__device__ float g_S[N_SAMP];            // sum_j pk[n,j]
__device__ float g_bias[N_SAMP * CH];

// ===========================================================================
// prep0: blocks [0,16): s_d;  blocks [16,32): per-sample d conv.
// ===========================================================================
__global__ void __launch_bounds__(512) prep0_kernel(
    const float* __restrict__ style,
    const float* __restrict__ dw_w,
    const float* __restrict__ dw_b)
{
    int b = blockIdx.x;
    int tid = threadIdx.x;
    int lane = tid & 31, warp = tid >> 5;

    if (b < 16) {                         // s_d: one thread per channel
        int n = b, c = tid;
        const float4* p = (const float4*)(style + (size_t)(n * 512 + c) * 16);
        float4 a = p[0], d4 = p[1], e = p[2], f = p[3];
        float s = a.x + a.y + a.z + a.w + d4.x + d4.y + d4.z + d4.w
                + e.x + e.y + e.z + e.w + f.x + f.y + f.z + f.w;
        g_sd[n * 512 + c] = s * (1.f / 16.f);
        return;
    }
    int n = b - 16;

    __shared__ float st[8192];            // style[n] 32 KB
    const float4* sp = (const float4*)(style + (size_t)n * 8192);
    for (int i = tid; i < 2048; i += 512) ((float4*)st)[i] = sp[i];
    __syncthreads();

    int j  = warp & 7;
    int p0 = warp >> 3;
    const float* wv = dw_w + (size_t)j * 2048;
    float bj = dw_b[j];
    for (int pos = p0; pos < 9; pos += 2) {
        int ky = pos / 3, kx = pos % 3;
        float acc = 0.f;
        #pragma unroll
        for (int k = 0; k < 16; k++) {
            int c = lane + 32 * k;
            const float* wc  = wv + c * 4;
            const float* stc = st + c * 16 + ky * 4 + kx;
            acc += wc[0] * stc[0] + wc[1] * stc[1]
                 + wc[2] * stc[4] + wc[3] * stc[5];
        }
        #pragma unroll
        for (int off = 16; off; off >>= 1)
            acc += __shfl_down_sync(0xffffffffu, acc, off);
        if (lane == 0) {
            float v = acc + bj;
            g_d[n * 72 + j * 9 + pos] = v >= 0.f ? v : 0.01f * v;
        }
    }
}

// ===========================================================================
// prep1: blocks [0,64): bias GEMV;  block 64: S.
// ===========================================================================
__global__ void __launch_bounds__(256) prep1_kernel(
    const float* __restrict__ pk_w,
    const float* __restrict__ pk_b,
    const float* __restrict__ pb_w,
    const float* __restrict__ pb_b)
{
    __shared__ float sh[8192];
    int b = blockIdx.x;
    int tid = threadIdx.x;
    int lane = tid & 31, warp = tid >> 5;

    if (b < 64) {
        for (int i = tid; i < 2048; i += 256)
            ((float4*)sh)[i] = ((const float4*)g_sd)[i];
        __syncthreads();
        int ch = b * 8 + warp;
        const float* row = pb_w + (size_t)ch * 512;
        float acc[N_SAMP];
        #pragma unroll
        for (int n = 0; n < N_SAMP; n++) acc[n] = 0.f;
        #pragma unroll
        for (int k = 0; k < 16; k++) {
            int c = lane + 32 * k;
            float wv = row[c];
            #pragma unroll
            for (int n = 0; n < N_SAMP; n++) acc[n] += wv * sh[n * 512 + c];
        }
        float bb = pb_b[ch];
        #pragma unroll
        for (int n = 0; n < N_SAMP; n++) {
            float a = acc[n];
            #pragma unroll
            for (int off = 16; off; off >>= 1)
                a += __shfl_down_sync(0xffffffffu, a, off);
            if (lane == 0) g_bias[n * 512 + ch] = a + bb;
        }
        return;
    }

    // S[n] = <s_d[n], wsum> + sum pk_b,  wsum[c] = sum_j pk_w[j][c]
    for (int c = tid; c < 512; c += 256) {
        float ws = 0.f;
        #pragma unroll
        for (int j = 0; j < 8; j++) ws += pk_w[j * 512 + c];
        sh[c] = ws;
    }
    __syncthreads();
    float bsum = 0.f;
    #pragma unroll
    for (int j = 0; j < 8; j++) bsum += pk_b[j];
    #pragma unroll
    for (int t = 0; t < 2; t++) {
        int n = warp + 8 * t;
        float acc = 0.f;
        #pragma unroll
        for (int k = 0; k < 16; k++) {
            int c = lane + 32 * k;
            acc += g_sd[n * 512 + c] * sh[c];
        }
        #pragma unroll
        for (int off = 16; off; off >>= 1)
            acc += __shfl_down_sync(0xffffffffu, acc, off);
        if (lane == 0) g_S[n] = acc + bsum;
    }
}

// ===========================================================================
// Main: cluster of 2 CTAs per (group, sample): top/bottom 32-row halves.
// Each CTA: 8 ch x 34 rows x 68 cols smem (72 KB). Stats via DSMEM exchange.
// Grid (2, 64, 16) x 256 threads, 3 CTAs/SM.
// ===========================================================================
__global__ void __launch_bounds__(256, 3) __cluster_dims__(2, 1, 1)
main_kernel(const float* __restrict__ content, float* __restrict__ out)
{
    extern __shared__ float s[];          // [8][SROWS][SCOLS]
    __shared__ float fd[72];
    __shared__ float fb[8], fm[8], fr[8];
    __shared__ float part[16];            // [sum x8, sq x8]
    __shared__ float fS_sh;

    int hf = blockIdx.x;                  // 0 = top half, 1 = bottom
    int g  = blockIdx.y;
    int n  = blockIdx.z;
    int tid = threadIdx.x;
    int lane = tid & 31, warp = tid >> 5;
    int cbase = n * 512 + g * 8;
    int r0 = hf * 32;                     // first output row of this half

    if (tid < 72)       fd[tid] = g_d[n * 72 + tid];
    else if (tid < 80)  fb[tid - 72] = g_bias[cbase + tid - 72];
    else if (tid == 80) fS_sh = g_S[n];

    // ---- load: warp = channel; rows r0-1 .. r0+32 (reflect), stats in regs ----
    int c = warp;
    const float* bc = content + (size_t)(cbase + c) * HW;
    float* sc = s + c * CHT;
    int sub = lane >> 4, q = lane & 15;
    float sum = 0.f, sq = 0.f;
    #pragma unroll
    for (int i = 0; i < 17; i++) {
        int lr = 2 * i + sub;
        int gr = r0 - 1 + lr;
        gr = gr < 0 ? 1 : (gr > 63 ? 62 : gr);
        float4 v = __ldcs((const float4*)(bc + gr * W + 4 * q));
        float* dst = sc + lr * SCOLS + 1 + 4 * q;
        dst[0] = v.x; dst[1] = v.y; dst[2] = v.z; dst[3] = v.w;
        if (lr >= 1 && lr <= 32) {
            sum += v.x + v.y + v.z + v.w;
            sq  += v.x * v.x + v.y * v.y + v.z * v.z + v.w * v.w;
        }
    }
    // halo columns: smem col 0 = global col -1 -> 1 ; smem col 65 = 64 -> 62
    for (int idx = tid; idx < 8 * SROWS * 2; idx += 256) {
        int c2  = idx / (SROWS * 2);
        int rem = idx % (SROWS * 2);
        int lr  = rem >> 1, side = rem & 1;
        int gr = r0 - 1 + lr;
        gr = gr < 0 ? 1 : (gr > 63 ? 62 : gr);
        const float* b2 = content + (size_t)(cbase + c2) * HW + gr * W;
        s[c2 * CHT + lr * SCOLS + (side ? 65 : 0)] = b2[side ? 62 : 1];
    }
    // ---- partial stats -> smem ----
    #pragma unroll
    for (int off = 16; off; off >>= 1) {
        sum += __shfl_down_sync(0xffffffffu, sum, off);
        sq  += __shfl_down_sync(0xffffffffu, sq,  off);
    }
    if (lane == 0) { part[c] = sum; part[8 + c] = sq; }
    __syncthreads();

    // ---- cluster barrier: tiles + partials visible across the pair ----
    asm volatile("barrier.cluster.arrive.aligned;" ::: "memory");
    asm volatile("barrier.cluster.wait.aligned;" ::: "memory");

    if (tid < 8) {
        uint32_t my = (uint32_t)__cvta_generic_to_shared(part);
        uint32_t pa;
        uint32_t peer = hf ^ 1;
        asm("mapa.shared::cluster.u32 %0, %1, %2;" : "=r"(pa) : "r"(my), "r"(peer));
        float ps, pq;
        asm("ld.shared::cluster.f32 %0, [%1];" : "=f"(ps) : "r"(pa + 4u * tid));
        asm("ld.shared::cluster.f32 %0, [%1];" : "=f"(pq) : "r"(pa + 4u * (8 + tid)));
        float S = part[tid] + ps;
        float Q = part[8 + tid] + pq;
        float mean = S * (1.f / HW);
        float var  = (Q - S * S * (1.f / HW)) * (1.f / (HW - 1));   // ddof=1
        fm[tid] = mean;
        fr[tid] = rsqrtf(var + 1e-5f);
    }
    __syncthreads();

    // ---- conv: 2 rows x 4 cols per thread ----
    int r2 = tid >> 4;                    // 0..15
    int w0 = (tid & 15) * 4;              // 0..60
    int h0 = 2 * r2;                      // local output rows h0, h0+1

    float D0[4] = {0.f, 0.f, 0.f, 0.f};
    float D1[4] = {0.f, 0.f, 0.f, 0.f};

    #pragma unroll
    for (int j = 0; j < 8; j++) {
        const float* sj = s + j * CHT;
        const float* fj = fd + j * 9;
        #pragma unroll
        for (int rr = 0; rr < 4; rr++) {
            const float* rp = sj + (h0 + rr) * SCOLS + w0;
            float4 a4 = *(const float4*)rp;
            float v4 = rp[4], v5 = rp[5];
            if (rr < 3) {
                float a = fj[rr * 3], b2 = fj[rr * 3 + 1], cc = fj[rr * 3 + 2];
                D0[0] += a * a4.x + b2 * a4.y + cc * a4.z;
                D0[1] += a * a4.y + b2 * a4.z + cc * a4.w;
                D0[2] += a * a4.z + b2 * a4.w + cc * v4;
                D0[3] += a * a4.w + b2 * v4   + cc * v5;
            }
            if (rr >= 1) {
                int kr = rr - 1;
                float a = fj[kr * 3], b2 = fj[kr * 3 + 1], cc = fj[kr * 3 + 2];
                D1[0] += a * a4.x + b2 * a4.y + cc * a4.z;
                D1[1] += a * a4.y + b2 * a4.z + cc * a4.w;
                D1[2] += a * a4.z + b2 * a4.w + cc * v4;
                D1[3] += a * a4.w + b2 * v4   + cc * v5;
            }
        }
    }

    float S = fS_sh;
    float* obase = out + (size_t)cbase * HW + (r0 + h0) * W + w0;

    #pragma unroll
    for (int o = 0; o < 8; o++) {
        const float* so = s + o * CHT;
        float mo = fm[o], ro = fr[o], bo = fb[o];
        float4 r0v, r1v;
        {
            const float* cen = so + (h0 + 1) * SCOLS + w0 + 1;
            float p0 = D0[0] * S + bo, p1 = D0[1] * S + bo;
            float p2 = D0[2] * S + bo, p3 = D0[3] * S + bo;
            p0 = p0 >= 0.f ? p0 : 0.01f * p0;
            p1 = p1 >= 0.f ? p1 : 0.01f * p1;
            p2 = p2 >= 0.f ? p2 : 0.01f * p2;
            p3 = p3 >= 0.f ? p3 : 0.01f * p3;
            r0v.x = (cen[0] - mo) * ro * p0;
            r0v.y = (cen[1] - mo) * ro * p1;
            r0v.z = (cen[2] - mo) * ro * p2;
            r0v.w = (cen[3] - mo) * ro * p3;
        }
        {
            const float* cen = so + (h0 + 2) * SCOLS + w0 + 1;
            float p0 = D1[0] * S + bo, p1 = D1[1] * S + bo;
            float p2 = D1[2] * S + bo, p3 = D1[3] * S + bo;
            p0 = p0 >= 0.f ? p0 : 0.01f * p0;
            p1 = p1 >= 0.f ? p1 : 0.01f * p1;
            p2 = p2 >= 0.f ? p2 : 0.01f * p2;
            p3 = p3 >= 0.f ? p3 : 0.01f * p3;
            r1v.x = (cen[0] - mo) * ro * p0;
            r1v.y = (cen[1] - mo) * ro * p1;
            r1v.z = (cen[2] - mo) * ro * p2;
            r1v.w = (cen[3] - mo) * ro * p3;
        }
        __stcs((float4*)(obase + (size_t)o * HW),     r0v);
        __stcs((float4*)(obase + (size_t)o * HW + W), r1v);
    }
}

// ===========================================================================
extern "C" void kernel_launch(void* const* d_in, const int* in_sizes, int n_in,
                              void* d_out, int out_size)
{
    const float* style   = (const float*)d_in[0];
    const float* content = (const float*)d_in[1];
    const float* dw_w    = (const float*)d_in[2];
    const float* dw_b    = (const float*)d_in[3];
    const float* pk_w    = (const float*)d_in[4];
    const float* pk_b    = (const float*)d_in[5];
    const float* pb_w    = (const float*)d_in[6];
    const float* pb_b    = (const float*)d_in[7];
    float* out = (float*)d_out;

    static bool attr_set = false;
    if (!attr_set) {
        cudaFuncSetAttribute(main_kernel,
                             cudaFuncAttributeMaxDynamicSharedMemorySize,
                             STILE * sizeof(float));
        attr_set = true;
    }

    prep0_kernel<<<32, 512>>>(style, dw_w, dw_b);
    prep1_kernel<<<65, 256>>>(pk_w, pk_b, pb_w, pb_b);
    main_kernel<<<dim3(2, NG, N_SAMP), 256, STILE * sizeof(float)>>>(content, out);
}

// round 7
// speedup vs baseline: 1.0855x; 1.0855x over previous
#include <cuda_runtime.h>
#include <cstdint>
#include <math.h>

#define CH 512
#define NG 64
#define N_SAMP 16
#define H 64
#define W 64
#define HW 4096

#define SROWS 66
#define SCOLS 68                          // 272B rows, 16B-aligned
#define CHT   (SROWS * SCOLS)             // 4488 floats per channel
#define STILE (8 * CHT)                   // 35904 floats = 143616 B

__device__ float g_d[N_SAMP * 72];        // leaky(d)[n, j, ky, kx]
__device__ float g_S[N_SAMP];             // sum_j pk[n,j]
__device__ float g_bias[N_SAMP * CH];

// ===========================================================================
// prep: ONE wide kernel, 144 blocks x 256 threads (~1 wave).
//   blocks [0,128)  : bias GEMV. block = (n, 64-channel chunk).
//   blocks [128,144): per-sample style conv -> d (72 dots) + S.
// ===========================================================================
__global__ void __launch_bounds__(256) prep_kernel(
    const float* __restrict__ style,
    const float* __restrict__ dw_w,
    const float* __restrict__ dw_b,
    const float* __restrict__ pk_w,
    const float* __restrict__ pk_b,
    const float* __restrict__ pb_w,
    const float* __restrict__ pb_b)
{
    __shared__ float sh[8192];
    int b   = blockIdx.x;
    int tid = threadIdx.x;
    int lane = tid & 31, warp = tid >> 5;

    if (b < 128) {
        // ---------------- bias ----------------
        int n = b >> 3, chunk = b & 7;
        // s_d[c] for this sample (style is L2-resident; 8x redundancy is fine)
        for (int c = tid; c < 512; c += 256) {
            const float4* p = (const float4*)(style + (size_t)(n * 512 + c) * 16);
            float4 a = p[0], d4 = p[1], e = p[2], f = p[3];
            float s = a.x + a.y + a.z + a.w + d4.x + d4.y + d4.z + d4.w
                    + e.x + e.y + e.z + e.w + f.x + f.y + f.z + f.w;
            sh[c] = s * (1.f / 16.f);
        }
        __syncthreads();
        int ch0 = chunk * 64 + warp * 8;      // 8 warps x 8 channels
        #pragma unroll
        for (int o = 0; o < 8; o++) {
            int ch = ch0 + o;
            const float* row = pb_w + (size_t)ch * 512;
            float acc = 0.f;
            #pragma unroll
            for (int k = 0; k < 16; k++) {
                int c = lane + 32 * k;
                acc += row[c] * sh[c];
            }
            #pragma unroll
            for (int off = 16; off; off >>= 1)
                acc += __shfl_down_sync(0xffffffffu, acc, off);
            if (lane == 0) g_bias[n * 512 + ch] = acc + pb_b[ch];
        }
        return;
    }

    // ---------------- style conv + S ----------------
    int n = b - 128;
    const float4* sp = (const float4*)(style + (size_t)n * 8192);
    for (int i = tid; i < 2048; i += 256) ((float4*)sh)[i] = sp[i];
    __syncthreads();

    // 8 warps cover 72 dots: o = warp, warp+8, ... (9 each)
    for (int o = warp; o < 72; o += 8) {
        int j = o / 9, pos = o % 9;
        int ky = pos / 3, kx = pos % 3;
        const float* wv = dw_w + (size_t)j * 2048;
        float acc = 0.f;
        #pragma unroll
        for (int k = 0; k < 16; k++) {
            int c = lane + 32 * k;
            const float* wc  = wv + c * 4;
            const float* stc = sh + c * 16 + ky * 4 + kx;
            acc += wc[0] * stc[0] + wc[1] * stc[1]
                 + wc[2] * stc[4] + wc[3] * stc[5];
        }
        #pragma unroll
        for (int off = 16; off; off >>= 1)
            acc += __shfl_down_sync(0xffffffffu, acc, off);
        if (lane == 0) {
            float v = acc + dw_b[j];
            g_d[n * 72 + o] = v >= 0.f ? v : 0.01f * v;
        }
    }

    // S[n] = sum_c s_d[c] * (sum_j pk_w[j][c]) + sum_j pk_b[j]
    if (warp == 0) {
        float acc = 0.f;
        #pragma unroll
        for (int k = 0; k < 16; k++) {
            int c = lane + 32 * k;
            float sdc = 0.f;
            #pragma unroll
            for (int p = 0; p < 16; p++) sdc += sh[c * 16 + p];
            sdc *= (1.f / 16.f);
            float ws = 0.f;
            #pragma unroll
            for (int j = 0; j < 8; j++) ws += pk_w[j * 512 + c];
            acc += sdc * ws;
        }
        #pragma unroll
        for (int off = 16; off; off >>= 1)
            acc += __shfl_down_sync(0xffffffffu, acc, off);
        if (lane == 0) {
            float bsum = 0.f;
            #pragma unroll
            for (int j = 0; j < 8; j++) bsum += pk_b[j];
            g_S[n] = acc + bsum;
        }
    }
}

// ===========================================================================
// Main: one block per (group, sample), full 8 x 66 x 68 tile (140 KB smem).
// Stats accumulated in registers during the load -> content read ONCE.
// Grid (64, 16) x 512 threads.
// ===========================================================================
__global__ void __launch_bounds__(512) main_kernel(
    const float* __restrict__ content, float* __restrict__ out)
{
    extern __shared__ float s[];          // [8][SROWS][SCOLS]
    __shared__ float fd[72];
    __shared__ float fb[8], fm[8], fr[8];
    __shared__ float red[32];
    __shared__ float fS_sh;

    int g = blockIdx.x;
    int n = blockIdx.y;
    int tid = threadIdx.x;
    int lane = tid & 31, warp = tid >> 5;
    int cbase = n * 512 + g * 8;

    if (tid < 72)       fd[tid] = g_d[n * 72 + tid];
    else if (tid < 80)  fb[tid - 72] = g_bias[cbase + tid - 72];
    else if (tid == 80) fS_sh = g_S[n];

    // ---- load: warp-pair per channel, reflect halo rows, stats in regs ----
    int c    = warp >> 1;
    int half = warp & 1;
    const float* bc = content + (size_t)(cbase + c) * HW;
    float* sc = s + c * CHT;
    float sum = 0.f, sq = 0.f;
    int sub = lane >> 4, q = lane & 15;
    #pragma unroll
    for (int i = 0; i < 17; i++) {
        int rr = 2 * i + sub;
        if (rr < 33) {
            int lr = half * 33 + rr;                          // smem row 0..65
            int gr = (lr == 0) ? 1 : (lr == 65 ? 62 : lr - 1);// reflect
            float4 v = *(const float4*)(bc + gr * W + 4 * q);
            float* dst = sc + lr * SCOLS + 1 + 4 * q;
            dst[0] = v.x; dst[1] = v.y; dst[2] = v.z; dst[3] = v.w;
            if (lr >= 1 && lr <= 64) {                        // interior only
                sum += v.x + v.y + v.z + v.w;
                sq  += v.x * v.x + v.y * v.y + v.z * v.z + v.w * v.w;
            }
        }
    }
    // halo columns: smem col 0 <- global col 1 ; smem col 65 <- global col 62
    for (int idx = tid; idx < 8 * SROWS; idx += 512) {
        int c2 = idx / SROWS, lr = idx % SROWS;
        int gr = (lr == 0) ? 1 : (lr == 65 ? 62 : lr - 1);
        const float* b2 = content + (size_t)(cbase + c2) * HW + gr * W;
        float* row = s + c2 * CHT + lr * SCOLS;
        row[0]  = b2[1];
        row[65] = b2[62];
    }
    // ---- stats reduce ----
    #pragma unroll
    for (int off = 16; off; off >>= 1) {
        sum += __shfl_down_sync(0xffffffffu, sum, off);
        sq  += __shfl_down_sync(0xffffffffu, sq,  off);
    }
    if (lane == 0) { red[warp] = sum; red[16 + warp] = sq; }
    __syncthreads();
    if (tid < 8) {
        float S = red[2 * tid] + red[2 * tid + 1];
        float Q = red[16 + 2 * tid] + red[16 + 2 * tid + 1];
        float mean = S * (1.f / HW);
        float var  = (Q - S * S * (1.f / HW)) * (1.f / (HW - 1));   // ddof=1
        fm[tid] = mean;
        fr[tid] = rsqrtf(var + 1e-5f);
    }
    __syncthreads();

    // ---- conv: 2 rows x 4 cols per thread ----
    int r2 = tid >> 4;                    // 0..31
    int w0 = (tid & 15) * 4;              // 0..60
    int h0 = 2 * r2;                      // output rows h0, h0+1

    float D0[4] = {0.f, 0.f, 0.f, 0.f};
    float D1[4] = {0.f, 0.f, 0.f, 0.f};

    #pragma unroll
    for (int j = 0; j < 8; j++) {
        const float* sj = s + j * CHT;
        const float* fj = fd + j * 9;
        #pragma unroll
        for (int rr = 0; rr < 4; rr++) {
            const float* rp = sj + (h0 + rr) * SCOLS + w0;
            float4 a4 = *(const float4*)rp;
            float v4 = rp[4], v5 = rp[5];
            if (rr < 3) {
                float a = fj[rr * 3], b2 = fj[rr * 3 + 1], cc = fj[rr * 3 + 2];
                D0[0] += a * a4.x + b2 * a4.y + cc * a4.z;
                D0[1] += a * a4.y + b2 * a4.z + cc * a4.w;
                D0[2] += a * a4.z + b2 * a4.w + cc * v4;
                D0[3] += a * a4.w + b2 * v4   + cc * v5;
            }
            if (rr >= 1) {
                int kr = rr - 1;
                float a = fj[kr * 3], b2 = fj[kr * 3 + 1], cc = fj[kr * 3 + 2];
                D1[0] += a * a4.x + b2 * a4.y + cc * a4.z;
                D1[1] += a * a4.y + b2 * a4.z + cc * a4.w;
                D1[2] += a * a4.z + b2 * a4.w + cc * v4;
                D1[3] += a * a4.w + b2 * v4   + cc * v5;
            }
        }
    }

    float S = fS_sh;
    float* obase = out + (size_t)cbase * HW + h0 * W + w0;

    #pragma unroll
    for (int o = 0; o < 8; o++) {
        const float* so = s + o * CHT;
        float mo = fm[o], ro = fr[o], bo = fb[o];
        float4 r0v, r1v;
        {
            const float* cen = so + (h0 + 1) * SCOLS + w0 + 1;
            float p0 = D0[0] * S + bo, p1 = D0[1] * S + bo;
            float p2 = D0[2] * S + bo, p3 = D0[3] * S + bo;
            p0 = p0 >= 0.f ? p0 : 0.01f * p0;
            p1 = p1 >= 0.f ? p1 : 0.01f * p1;
            p2 = p2 >= 0.f ? p2 : 0.01f * p2;
            p3 = p3 >= 0.f ? p3 : 0.01f * p3;
            r0v.x = (cen[0] - mo) * ro * p0;
            r0v.y = (cen[1] - mo) * ro * p1;
            r0v.z = (cen[2] - mo) * ro * p2;
            r0v.w = (cen[3] - mo) * ro * p3;
        }
        {
            const float* cen = so + (h0 + 2) * SCOLS + w0 + 1;
            float p0 = D1[0] * S + bo, p1 = D1[1] * S + bo;
            float p2 = D1[2] * S + bo, p3 = D1[3] * S + bo;
            p0 = p0 >= 0.f ? p0 : 0.01f * p0;
            p1 = p1 >= 0.f ? p1 : 0.01f * p1;
            p2 = p2 >= 0.f ? p2 : 0.01f * p2;
            p3 = p3 >= 0.f ? p3 : 0.01f * p3;
            r1v.x = (cen[0] - mo) * ro * p0;
            r1v.y = (cen[1] - mo) * ro * p1;
            r1v.z = (cen[2] - mo) * ro * p2;
            r1v.w = (cen[3] - mo) * ro * p3;
        }
        __stcs((float4*)(obase + (size_t)o * HW),     r0v);
        __stcs((float4*)(obase + (size_t)o * HW + W), r1v);
    }
}

// ===========================================================================
extern "C" void kernel_launch(void* const* d_in, const int* in_sizes, int n_in,
                              void* d_out, int out_size)
{
    const float* style   = (const float*)d_in[0];
    const float* content = (const float*)d_in[1];
    const float* dw_w    = (const float*)d_in[2];
    const float* dw_b    = (const float*)d_in[3];
    const float* pk_w    = (const float*)d_in[4];
    const float* pk_b    = (const float*)d_in[5];
    const float* pb_w    = (const float*)d_in[6];
    const float* pb_b    = (const float*)d_in[7];
    float* out = (float*)d_out;

    static bool attr_set = false;
    if (!attr_set) {
        cudaFuncSetAttribute(main_kernel,
                             cudaFuncAttributeMaxDynamicSharedMemorySize,
                             STILE * sizeof(float));
        attr_set = true;
    }

    prep_kernel<<<144, 256>>>(style, dw_w, dw_b, pk_w, pk_b, pb_w, pb_b);
    main_kernel<<<dim3(NG, N_SAMP), 512, STILE * sizeof(float)>>>(content, out);
}

// round 8
// speedup vs baseline: 1.1497x; 1.0591x over previous
#include <cuda_runtime.h>
#include <cstdint>
#include <math.h>

#define CH 512
#define NG 64
#define N_SAMP 16
#define H 64
#define W 64
#define HW 4096

#define SROWS 66
#define SCOLS 72                          // interior at col 4 -> 16B-aligned
#define CHT   (SROWS * SCOLS)             // 4752 floats
#define STILE (8 * CHT)                   // 38016 floats = 152064 B

// ===========================================================================
// ONE fused kernel. Grid (64, 16) x 512 threads.
// Per block: prep (d, bias, S) recomputed locally, content tile load with
// in-register stats, conv + pointwise collapse + instance norm + multiply.
// ===========================================================================
__global__ void __launch_bounds__(512) fused_kernel(
    const float* __restrict__ content,
    const float* __restrict__ style,
    const float* __restrict__ dw_w,
    const float* __restrict__ dw_b,
    const float* __restrict__ pk_w,
    const float* __restrict__ pk_b,
    const float* __restrict__ pb_w,
    const float* __restrict__ pb_b,
    float* __restrict__ out)
{
    extern __shared__ float s[];          // [8][SROWS][SCOLS]
    __shared__ float sd[512];             // style spatial mean
    __shared__ float dred[16 * 72];       // per-warp d partials
    __shared__ float fd[72];
    __shared__ float fb[8], fm[8], fr[8];
    __shared__ float red[32];
    __shared__ float fS_sh;

    int g = blockIdx.x;
    int n = blockIdx.y;
    int tid = threadIdx.x;
    int lane = tid & 31, warp = tid >> 5;
    int cbase = n * 512 + g * 8;

    // ================= prep: d partials, one thread per style channel ======
    {
        int c = tid;
        const float4* stp = (const float4*)(style + (size_t)(n * 512 + c) * 16);
        float4 s0 = stp[0], s1 = stp[1], s2 = stp[2], s3 = stp[3];
        float st[16] = { s0.x, s0.y, s0.z, s0.w,  s1.x, s1.y, s1.z, s1.w,
                         s2.x, s2.y, s2.z, s2.w,  s3.x, s3.y, s3.z, s3.w };
        float tot = 0.f;
        #pragma unroll
        for (int p = 0; p < 16; p++) tot += st[p];
        sd[c] = tot * (1.f / 16.f);

        #pragma unroll
        for (int pass = 0; pass < 2; pass++) {
            float acc[36];
            #pragma unroll
            for (int jj = 0; jj < 4; jj++) {
                float4 w = ((const float4*)dw_w)[(size_t)(pass * 4 + jj) * 512 + c];
                #pragma unroll
                for (int ky = 0; ky < 3; ky++)
                    #pragma unroll
                    for (int kx = 0; kx < 3; kx++)
                        acc[jj * 9 + ky * 3 + kx] =
                              w.x * st[ky * 4 + kx]     + w.y * st[ky * 4 + kx + 1]
                            + w.z * st[ky * 4 + kx + 4] + w.w * st[ky * 4 + kx + 5];
            }
            #pragma unroll
            for (int i = 0; i < 36; i++) {
                #pragma unroll
                for (int off = 16; off; off >>= 1)
                    acc[i] += __shfl_xor_sync(0xffffffffu, acc[i], off);
            }
            for (int i = lane; i < 36; i += 32)
                dred[warp * 72 + pass * 36 + i] = acc[i];
        }
    }
    __syncthreads();

    if (tid < 72) {
        float v = 0.f;
        #pragma unroll
        for (int w = 0; w < 16; w++) v += dred[w * 72 + tid];
        v += dw_b[tid / 9];
        fd[tid] = v >= 0.f ? v : 0.01f * v;        // leaky
    }
    if (warp < 8) {                                 // bias dot for channel g*8+warp
        const float* row = pb_w + (size_t)(g * 8 + warp) * 512;
        float acc = 0.f;
        #pragma unroll
        for (int k = 0; k < 16; k++) {
            int c2 = lane + 32 * k;
            acc += row[c2] * sd[c2];
        }
        #pragma unroll
        for (int off = 16; off; off >>= 1)
            acc += __shfl_down_sync(0xffffffffu, acc, off);
        if (lane == 0) fb[warp] = acc + pb_b[g * 8 + warp];
    } else if (warp == 8) {                         // S
        float acc = 0.f;
        #pragma unroll
        for (int k = 0; k < 16; k++) {
            int c2 = lane + 32 * k;
            float ws = 0.f;
            #pragma unroll
            for (int j = 0; j < 8; j++) ws += pk_w[j * 512 + c2];
            acc += sd[c2] * ws;
        }
        #pragma unroll
        for (int off = 16; off; off >>= 1)
            acc += __shfl_down_sync(0xffffffffu, acc, off);
        if (lane == 0) {
            float bsum = 0.f;
            #pragma unroll
            for (int j = 0; j < 8; j++) bsum += pk_b[j];
            fS_sh = acc + bsum;
        }
    }
    // (no sync: fd/fb/fS consumed only after the syncs below)

    // ================= content tile load, stats in registers ===============
    {
        int c    = warp >> 1;
        int half = warp & 1;
        const float* bc = content + (size_t)(cbase + c) * HW;
        float* sc = s + c * CHT;
        float sum = 0.f, sq = 0.f;
        int sub = lane >> 4, q = lane & 15;
        #pragma unroll
        for (int i = 0; i < 17; i++) {
            int rr = 2 * i + sub;
            if (rr < 33) {
                int lr = half * 33 + rr;                           // 0..65
                int gr = (lr == 0) ? 1 : (lr == 65 ? 62 : lr - 1); // reflect
                float4 v = *(const float4*)(bc + gr * W + 4 * q);
                *(float4*)(sc + lr * SCOLS + 4 + 4 * q) = v;       // STS.128
                if (lr >= 1 && lr <= 64) {
                    sum += v.x + v.y + v.z + v.w;
                    sq  += v.x * v.x + v.y * v.y + v.z * v.z + v.w * v.w;
                }
            }
        }
        // halo columns: col 3 <- global col 1 ; col 68 <- global col 62
        for (int idx = tid; idx < 8 * SROWS; idx += 512) {
            int c2 = idx / SROWS, lr = idx % SROWS;
            int gr = (lr == 0) ? 1 : (lr == 65 ? 62 : lr - 1);
            const float* b2 = content + (size_t)(cbase + c2) * HW + gr * W;
            float* row = s + c2 * CHT + lr * SCOLS;
            row[3]  = b2[1];
            row[68] = b2[62];
        }
        #pragma unroll
        for (int off = 16; off; off >>= 1) {
            sum += __shfl_down_sync(0xffffffffu, sum, off);
            sq  += __shfl_down_sync(0xffffffffu, sq,  off);
        }
        if (lane == 0) { red[warp] = sum; red[16 + warp] = sq; }
    }
    __syncthreads();
    if (tid < 8) {
        float S = red[2 * tid] + red[2 * tid + 1];
        float Q = red[16 + 2 * tid] + red[16 + 2 * tid + 1];
        float mean = S * (1.f / HW);
        float var  = (Q - S * S * (1.f / HW)) * (1.f / (HW - 1));  // ddof=1
        fm[tid] = mean;
        fr[tid] = rsqrtf(var + 1e-5f);
    }
    __syncthreads();

    // ================= conv: 2 rows x 4 cols per thread ====================
    int r2 = tid >> 4;                    // 0..31
    int q4 = (tid & 15) * 4;              // output col base 0..60
    int h0 = 2 * r2;                      // output rows h0, h0+1

    float D0[4] = {0.f, 0.f, 0.f, 0.f};
    float D1[4] = {0.f, 0.f, 0.f, 0.f};

    #pragma unroll
    for (int j = 0; j < 8; j++) {
        const float* sj = s + j * CHT;
        const float* fj = fd + j * 9;
        #pragma unroll
        for (int rr = 0; rr < 4; rr++) {
            const float* rp = sj + (h0 + rr) * SCOLS + q4;
            float vL = rp[3];
            float4 f4 = *(const float4*)(rp + 4);   // aligned LDS.128
            float vR = rp[8];
            if (rr < 3) {
                float a = fj[rr * 3], b2 = fj[rr * 3 + 1], cc = fj[rr * 3 + 2];
                D0[0] += a * vL   + b2 * f4.x + cc * f4.y;
                D0[1] += a * f4.x + b2 * f4.y + cc * f4.z;
                D0[2] += a * f4.y + b2 * f4.z + cc * f4.w;
                D0[3] += a * f4.z + b2 * f4.w + cc * vR;
            }
            if (rr >= 1) {
                int kr = rr - 1;
                float a = fj[kr * 3], b2 = fj[kr * 3 + 1], cc = fj[kr * 3 + 2];
                D1[0] += a * vL   + b2 * f4.x + cc * f4.y;
                D1[1] += a * f4.x + b2 * f4.y + cc * f4.z;
                D1[2] += a * f4.y + b2 * f4.z + cc * f4.w;
                D1[3] += a * f4.z + b2 * f4.w + cc * vR;
            }
        }
    }

    float S = fS_sh;
    float* obase = out + (size_t)cbase * HW + h0 * W + q4;

    #pragma unroll
    for (int o = 0; o < 8; o++) {
        const float* so = s + o * CHT;
        float mo = fm[o], ro = fr[o], bo = fb[o];
        float4 r0v, r1v;
        {
            float4 cen = *(const float4*)(so + (h0 + 1) * SCOLS + 4 + q4);
            float p0 = D0[0] * S + bo, p1 = D0[1] * S + bo;
            float p2 = D0[2] * S + bo, p3 = D0[3] * S + bo;
            p0 = p0 >= 0.f ? p0 : 0.01f * p0;
            p1 = p1 >= 0.f ? p1 : 0.01f * p1;
            p2 = p2 >= 0.f ? p2 : 0.01f * p2;
            p3 = p3 >= 0.f ? p3 : 0.01f * p3;
            r0v.x = (cen.x - mo) * ro * p0;
            r0v.y = (cen.y - mo) * ro * p1;
            r0v.z = (cen.z - mo) * ro * p2;
            r0v.w = (cen.w - mo) * ro * p3;
        }
        {
            float4 cen = *(const float4*)(so + (h0 + 2) * SCOLS + 4 + q4);
            float p0 = D1[0] * S + bo, p1 = D1[1] * S + bo;
            float p2 = D1[2] * S + bo, p3 = D1[3] * S + bo;
            p0 = p0 >= 0.f ? p0 : 0.01f * p0;
            p1 = p1 >= 0.f ? p1 : 0.01f * p1;
            p2 = p2 >= 0.f ? p2 : 0.01f * p2;
            p3 = p3 >= 0.f ? p3 : 0.01f * p3;
            r1v.x = (cen.x - mo) * ro * p0;
            r1v.y = (cen.y - mo) * ro * p1;
            r1v.z = (cen.z - mo) * ro * p2;
            r1v.w = (cen.w - mo) * ro * p3;
        }
        __stcs((float4*)(obase + (size_t)o * HW),     r0v);
        __stcs((float4*)(obase + (size_t)o * HW + W), r1v);
    }
}

// ===========================================================================
extern "C" void kernel_launch(void* const* d_in, const int* in_sizes, int n_in,
                              void* d_out, int out_size)
{
    const float* style   = (const float*)d_in[0];
    const float* content = (const float*)d_in[1];
    const float* dw_w    = (const float*)d_in[2];
    const float* dw_b    = (const float*)d_in[3];
    const float* pk_w    = (const float*)d_in[4];
    const float* pk_b    = (const float*)d_in[5];
    const float* pb_w    = (const float*)d_in[6];
    const float* pb_b    = (const float*)d_in[7];
    float* out = (float*)d_out;

    static bool attr_set = false;
    if (!attr_set) {
        cudaFuncSetAttribute(fused_kernel,
                             cudaFuncAttributeMaxDynamicSharedMemorySize,
                             STILE * sizeof(float));
        attr_set = true;
    }

    fused_kernel<<<dim3(NG, N_SAMP), 512, STILE * sizeof(float)>>>(
        content, style, dw_w, dw_b, pk_w, pk_b, pb_w, pb_b, out);
}